// round 1
// baseline (speedup 1.0000x reference)
#include <cuda_runtime.h>

#define Hh 64
#define Tt 512
#define BPB 32      // batches per block
#define NBT 4       // batches per thread
#define NTHREADS 512
#define TX 32       // x timesteps staged per chunk

__device__ __forceinline__ float sigmoid_f(float x) {
    x = fminf(fmaxf(x, -30.f), 30.f);
    float e = __expf(-x);
    return __fdividef(1.f, 1.f + e);
}
__device__ __forceinline__ float tanh_f(float x) {
    x = fminf(fmaxf(x, -15.f), 15.f);
    float e = __expf(-2.f * x);
    return __fdividef(1.f - e, 1.f + e);
}

extern "C" __global__ void __launch_bounds__(NTHREADS, 1)
gru_persistent_kernel(const float* __restrict__ x,
                      const float* __restrict__ W_ih,
                      const float* __restrict__ W_hh,
                      const float* __restrict__ b_ih,
                      const float* __restrict__ b_hh,
                      const float* __restrict__ W_out,
                      const float* __restrict__ b_out,
                      float* __restrict__ out)
{
    extern __shared__ float sm[];
    float* Wr = sm;                      // [64][64]  Wr[k*64+j] = W_hh[j][k]
    float* Wz = Wr + Hh * Hh;
    float* Wn = Wz + Hh * Hh;
    float* hb = Wn + Hh * Hh;            // [2][32][64]
    float* xs = hb + 2 * BPB * Hh;       // [32][TX]

    const int tid = threadIdx.x;
    const int j = tid & 63;
    const int g = tid >> 6;              // 0..7, batch group
    const int bBase = blockIdx.x * BPB;

    // Load W_hh transposed into shared (one-time; L2-resident across blocks).
    for (int idx = tid; idx < Hh * Hh; idx += NTHREADS) {
        int k = idx >> 6, jj = idx & 63;
        Wr[idx] = W_hh[jj * Hh + k];
        Wz[idx] = W_hh[(Hh + jj) * Hh + k];
        Wn[idx] = W_hh[(2 * Hh + jj) * Hh + k];
    }
    // Zero h buffer 0
    for (int idx = tid; idx < BPB * Hh; idx += NTHREADS)
        hb[idx] = 0.f;

    // Per-thread constants (I=1: x projection is a scalar multiply)
    const float wir = W_ih[j];
    const float wiz = W_ih[Hh + j];
    const float win = W_ih[2 * Hh + j];
    const float cr  = b_ih[j]          + b_hh[j];
    const float cz  = b_ih[Hh + j]     + b_hh[Hh + j];
    const float cnx = b_ih[2 * Hh + j];
    const float cnh = b_hh[2 * Hh + j];

    float hprev[NBT];
    #pragma unroll
    for (int i = 0; i < NBT; ++i) hprev[i] = 0.f;

    int cur = 0;

    for (int t = 0; t < Tt; ++t) {
        if ((t & (TX - 1)) == 0) {
            // Stage next TX timesteps of x for this block's 32 batches.
            // Prior chunk's reads all happened before the end-of-step barrier.
            #pragma unroll
            for (int r = 0; r < (BPB * TX) / NTHREADS; ++r) {
                int idx = tid + r * NTHREADS;
                int bi = idx >> 5;       // /TX
                int tt = idx & (TX - 1);
                xs[bi * TX + tt] = x[(bBase + bi) * Tt + t + tt];
            }
            __syncthreads();             // publishes xs (and init writes at t=0)
        }

        float ar[NBT], az[NBT], an[NBT];
        #pragma unroll
        for (int i = 0; i < NBT; ++i) { ar[i] = 0.f; az[i] = 0.f; an[i] = 0.f; }

        const float* hcur = hb + cur * BPB * Hh + (g * NBT) * Hh;

        #pragma unroll
        for (int k = 0; k < Hh; k += 4) {
            float wr0 = Wr[(k + 0) * Hh + j];
            float wr1 = Wr[(k + 1) * Hh + j];
            float wr2 = Wr[(k + 2) * Hh + j];
            float wr3 = Wr[(k + 3) * Hh + j];
            float wz0 = Wz[(k + 0) * Hh + j];
            float wz1 = Wz[(k + 1) * Hh + j];
            float wz2 = Wz[(k + 2) * Hh + j];
            float wz3 = Wz[(k + 3) * Hh + j];
            float wn0 = Wn[(k + 0) * Hh + j];
            float wn1 = Wn[(k + 1) * Hh + j];
            float wn2 = Wn[(k + 2) * Hh + j];
            float wn3 = Wn[(k + 3) * Hh + j];
            #pragma unroll
            for (int i = 0; i < NBT; ++i) {
                float4 h4 = *reinterpret_cast<const float4*>(hcur + i * Hh + k);
                ar[i] = fmaf(h4.x, wr0, ar[i]);
                ar[i] = fmaf(h4.y, wr1, ar[i]);
                ar[i] = fmaf(h4.z, wr2, ar[i]);
                ar[i] = fmaf(h4.w, wr3, ar[i]);
                az[i] = fmaf(h4.x, wz0, az[i]);
                az[i] = fmaf(h4.y, wz1, az[i]);
                az[i] = fmaf(h4.z, wz2, az[i]);
                az[i] = fmaf(h4.w, wz3, az[i]);
                an[i] = fmaf(h4.x, wn0, an[i]);
                an[i] = fmaf(h4.y, wn1, an[i]);
                an[i] = fmaf(h4.z, wn2, an[i]);
                an[i] = fmaf(h4.w, wn3, an[i]);
            }
        }

        const int tt = t & (TX - 1);
        float* hnext = hb + (cur ^ 1) * BPB * Hh;
        #pragma unroll
        for (int i = 0; i < NBT; ++i) {
            const int bl = g * NBT + i;
            float xv = xs[bl * TX + tt];
            float r  = sigmoid_f(fmaf(xv, wir, ar[i] + cr));
            float z  = sigmoid_f(fmaf(xv, wiz, az[i] + cz));
            float n  = tanh_f(fmaf(xv, win, cnx) + r * (an[i] + cnh));
            float hn = fmaf(z, hprev[i] - n, n);
            hprev[i] = hn;
            hnext[bl * Hh + j] = hn;
        }
        __syncthreads();                 // publishes h(t+1)
        cur ^= 1;
    }

    // Output: out[b] = h_last[b] . W_out + b_out
    if (tid < BPB) {
        const float* hl = hb + cur * BPB * Hh + tid * Hh;
        float s = b_out[0];
        #pragma unroll
        for (int k = 0; k < Hh; ++k)
            s = fmaf(hl[k], W_out[k], s);
        out[bBase + tid] = s;
    }
}

extern "C" void kernel_launch(void* const* d_in, const int* in_sizes, int n_in,
                              void* d_out, int out_size)
{
    const float* x     = (const float*)d_in[0];
    const float* W_ih  = (const float*)d_in[1];
    const float* W_hh  = (const float*)d_in[2];
    const float* b_ih  = (const float*)d_in[3];
    const float* b_hh  = (const float*)d_in[4];
    const float* W_out = (const float*)d_in[5];
    const float* b_out = (const float*)d_in[6];
    float* out = (float*)d_out;

    const size_t smem = (size_t)(3 * Hh * Hh + 2 * BPB * Hh + BPB * TX) * sizeof(float);
    cudaFuncSetAttribute(gru_persistent_kernel,
                         cudaFuncAttributeMaxDynamicSharedMemorySize, (int)smem);

    const int B = 4096;
    gru_persistent_kernel<<<B / BPB, NTHREADS, smem>>>(
        x, W_ih, W_hh, b_ih, b_hh, W_out, b_out, out);
}

// round 2
// speedup vs baseline: 1.6970x; 1.6970x over previous
#include <cuda_runtime.h>

#define Hh 64
#define Tt 512
#define BPB 32      // batches per block
#define NBT 4       // batches per thread
#define NTHREADS 512
#define TX 32       // x timesteps staged per chunk

typedef unsigned long long ull;

// Packed dual-FMA: d = a * b + c elementwise on {f32,f32} pairs (SASS FFMA2).
__device__ __forceinline__ ull ffma2(ull a, ull b, ull c) {
    ull d;
    asm("fma.rn.f32x2 %0, %1, %2, %3;" : "=l"(d) : "l"(a), "l"(b), "l"(c));
    return d;
}
__device__ __forceinline__ float2 unpk(ull v) {
    float2 f;
    asm("mov.b64 {%0, %1}, %2;" : "=f"(f.x), "=f"(f.y) : "l"(v));
    return f;
}

__device__ __forceinline__ float sigmoid_f(float x) {
    x = fminf(fmaxf(x, -30.f), 30.f);
    float e = __expf(-x);
    return __fdividef(1.f, 1.f + e);
}
__device__ __forceinline__ float tanh_f(float x) {
    x = fminf(fmaxf(x, -15.f), 15.f);
    float e = __expf(-2.f * x);
    return __fdividef(1.f - e, 1.f + e);
}

extern "C" __global__ void __launch_bounds__(NTHREADS, 1)
gru_persistent_kernel(const float* __restrict__ x,
                      const float* __restrict__ W_ih,
                      const float* __restrict__ W_hh,
                      const float* __restrict__ b_ih,
                      const float* __restrict__ b_hh,
                      const float* __restrict__ W_out,
                      const float* __restrict__ b_out,
                      float* __restrict__ out)
{
    extern __shared__ float sm[];
    // Prepacked weights: per gate, [32 kpairs][64 j] of float2 {W[2kp][j], W[2kp+1][j]}
    float2* Wr2 = reinterpret_cast<float2*>(sm);            // 2048 float2
    float2* Wz2 = Wr2 + 32 * Hh;
    float2* Wn2 = Wz2 + 32 * Hh;
    float*  hb  = sm + 3 * 2 * 32 * Hh;                     // [2][32][64] floats
    float*  xs  = hb + 2 * BPB * Hh;                        // [32][TX]

    const int tid = threadIdx.x;
    const int j = tid & 63;
    const int g = tid >> 6;              // 0..7, batch group
    const int bBase = blockIdx.x * BPB;

    // Prepack W_hh into shared as k-pair-interleaved float2, transposed to [kp][j].
    // W_hh row-major [3H][H]: W_hh[(gate*64 + j)*64 + k]
    for (int idx = tid; idx < 3 * 32 * Hh; idx += NTHREADS) {
        int gate = idx >> 11;            // /2048
        int rem  = idx & 2047;
        int kp   = rem >> 6;
        int jj   = rem & 63;
        const float* row = W_hh + (gate * Hh + jj) * Hh;
        float2 w = make_float2(row[2 * kp], row[2 * kp + 1]);
        (gate == 0 ? Wr2 : gate == 1 ? Wz2 : Wn2)[kp * Hh + jj] = w;
    }
    // Zero h buffer 0
    for (int idx = tid; idx < BPB * Hh; idx += NTHREADS)
        hb[idx] = 0.f;

    // Per-thread constants (I=1: x projection is a scalar multiply)
    const float wir = W_ih[j];
    const float wiz = W_ih[Hh + j];
    const float win = W_ih[2 * Hh + j];
    const float cr  = b_ih[j]          + b_hh[j];
    const float cz  = b_ih[Hh + j]     + b_hh[Hh + j];
    const float cnx = b_ih[2 * Hh + j];
    const float cnh = b_hh[2 * Hh + j];

    float hprev[NBT];
    #pragma unroll
    for (int i = 0; i < NBT; ++i) hprev[i] = 0.f;

    int cur = 0;

    for (int t = 0; t < Tt; ++t) {
        if ((t & (TX - 1)) == 0) {
            #pragma unroll
            for (int r = 0; r < (BPB * TX) / NTHREADS; ++r) {
                int idx = tid + r * NTHREADS;
                int bi = idx >> 5;
                int tt = idx & (TX - 1);
                xs[bi * TX + tt] = x[(bBase + bi) * Tt + t + tt];
            }
            __syncthreads();             // publishes xs (and init writes at t=0)
        }

        // Packed accumulators: {sum over even k, sum over odd k}
        ull acc_r[NBT], acc_z[NBT], acc_n[NBT];
        #pragma unroll
        for (int i = 0; i < NBT; ++i) { acc_r[i] = 0ull; acc_z[i] = 0ull; acc_n[i] = 0ull; }

        const float* hcur = hb + cur * BPB * Hh + (g * NBT) * Hh;

        #pragma unroll
        for (int kp = 0; kp < 32; kp += 2) {
            // Weights for k = 2kp..2kp+3 at this thread's j (8B loads, conflict-free)
            ull wr0 = *reinterpret_cast<const ull*>(Wr2 + (kp    ) * Hh + j);
            ull wr1 = *reinterpret_cast<const ull*>(Wr2 + (kp + 1) * Hh + j);
            ull wz0 = *reinterpret_cast<const ull*>(Wz2 + (kp    ) * Hh + j);
            ull wz1 = *reinterpret_cast<const ull*>(Wz2 + (kp + 1) * Hh + j);
            ull wn0 = *reinterpret_cast<const ull*>(Wn2 + (kp    ) * Hh + j);
            ull wn1 = *reinterpret_cast<const ull*>(Wn2 + (kp + 1) * Hh + j);
            #pragma unroll
            for (int i = 0; i < NBT; ++i) {
                // {h[2kp], h[2kp+1]}, {h[2kp+2], h[2kp+3]} — warp-uniform broadcast
                ulonglong2 h2 = *reinterpret_cast<const ulonglong2*>(hcur + i * Hh + 2 * kp);
                acc_r[i] = ffma2(h2.x, wr0, acc_r[i]);
                acc_r[i] = ffma2(h2.y, wr1, acc_r[i]);
                acc_z[i] = ffma2(h2.x, wz0, acc_z[i]);
                acc_z[i] = ffma2(h2.y, wz1, acc_z[i]);
                acc_n[i] = ffma2(h2.x, wn0, acc_n[i]);
                acc_n[i] = ffma2(h2.y, wn1, acc_n[i]);
            }
        }

        const int tt = t & (TX - 1);
        float* hnext = hb + (cur ^ 1) * BPB * Hh;
        #pragma unroll
        for (int i = 0; i < NBT; ++i) {
            const int bl = g * NBT + i;
            float2 pr = unpk(acc_r[i]);
            float2 pz = unpk(acc_z[i]);
            float2 pn = unpk(acc_n[i]);
            float ar = pr.x + pr.y;
            float az = pz.x + pz.y;
            float an = pn.x + pn.y;
            float xv = xs[bl * TX + tt];
            float r  = sigmoid_f(fmaf(xv, wir, ar + cr));
            float z  = sigmoid_f(fmaf(xv, wiz, az + cz));
            float n  = tanh_f(fmaf(xv, win, cnx) + r * (an + cnh));
            float hn = fmaf(z, hprev[i] - n, n);
            hprev[i] = hn;
            hnext[bl * Hh + j] = hn;
        }
        __syncthreads();                 // publishes h(t+1)
        cur ^= 1;
    }

    // Output: out[b] = h_last[b] . W_out + b_out
    if (tid < BPB) {
        const float* hl = hb + cur * BPB * Hh + tid * Hh;
        float s = b_out[0];
        #pragma unroll
        for (int k = 0; k < Hh; ++k)
            s = fmaf(hl[k], W_out[k], s);
        out[bBase + tid] = s;
    }
}

extern "C" void kernel_launch(void* const* d_in, const int* in_sizes, int n_in,
                              void* d_out, int out_size)
{
    const float* x     = (const float*)d_in[0];
    const float* W_ih  = (const float*)d_in[1];
    const float* W_hh  = (const float*)d_in[2];
    const float* b_ih  = (const float*)d_in[3];
    const float* b_hh  = (const float*)d_in[4];
    const float* W_out = (const float*)d_in[5];
    const float* b_out = (const float*)d_in[6];
    float* out = (float*)d_out;

    const size_t smem = (size_t)(3 * 2 * 32 * Hh + 2 * BPB * Hh + BPB * TX) * sizeof(float);
    cudaFuncSetAttribute(gru_persistent_kernel,
                         cudaFuncAttributeMaxDynamicSharedMemorySize, (int)smem);

    const int B = 4096;
    gru_persistent_kernel<<<B / BPB, NTHREADS, smem>>>(
        x, W_ih, W_hh, b_ih, b_hh, W_out, b_out, out);
}

// round 3
// speedup vs baseline: 1.9855x; 1.1700x over previous
#include <cuda_runtime.h>

#define Hh 64
#define Tt 512
#define BPB 32      // batches per block
#define NBT 4       // batches per thread (= batches per 64-thread group)
#define NTHREADS 512
#define TX 32       // x timesteps staged per chunk

typedef unsigned long long ull;

__device__ __forceinline__ ull ffma2(ull a, ull b, ull c) {
    ull d;
    asm("fma.rn.f32x2 %0, %1, %2, %3;" : "=l"(d) : "l"(a), "l"(b), "l"(c));
    return d;
}
__device__ __forceinline__ float2 unpk(ull v) {
    float2 f;
    asm("mov.b64 {%0, %1}, %2;" : "=f"(f.x), "=f"(f.y) : "l"(v));
    return f;
}
__device__ __forceinline__ void grpbar(int id) {
    asm volatile("bar.sync %0, 64;" :: "r"(id) : "memory");
}

__device__ __forceinline__ float sigmoid_f(float x) {
    x = fminf(fmaxf(x, -30.f), 30.f);
    float e = __expf(-x);
    return __fdividef(1.f, 1.f + e);
}
__device__ __forceinline__ float tanh_f(float x) {
    x = fminf(fmaxf(x, -15.f), 15.f);
    float e = __expf(-2.f * x);
    return __fdividef(1.f - e, 1.f + e);
}

extern "C" __global__ void __launch_bounds__(NTHREADS, 1)
gru_persistent_kernel(const float* __restrict__ x,
                      const float* __restrict__ W_ih,
                      const float* __restrict__ W_hh,
                      const float* __restrict__ b_ih,
                      const float* __restrict__ b_hh,
                      const float* __restrict__ W_out,
                      const float* __restrict__ b_out,
                      float* __restrict__ out)
{
    extern __shared__ float sm[];
    // Weights packed as [gate][kq][j] float4 = {W[4kq..4kq+3][j]}; 16 kq x 64 j per gate.
    ulonglong2* W4 = reinterpret_cast<ulonglong2*>(sm);     // 3*16*64 entries, 48KB
    float* hb = sm + 3 * 16 * Hh * 4;                       // [2][32][64]
    float* xs = hb + 2 * BPB * Hh;                          // [32][TX]

    const int tid = threadIdx.x;
    const int j = tid & 63;
    const int g = tid >> 6;              // 0..7 group, 2 warps each
    const int lt = tid & 63;             // lane within group
    const int bBase = blockIdx.x * BPB;

    // Prepack W_hh: W4[gate*1024 + kq*64 + j] = {W_hh[(gate*64+j)*64 + 4kq + 0..3]}
    {
        float4* W4f = reinterpret_cast<float4*>(sm);
        for (int idx = tid; idx < 3 * 16 * Hh; idx += NTHREADS) {
            int gate = idx >> 10;
            int rem  = idx & 1023;
            int kq   = rem >> 6;
            int jj   = rem & 63;
            const float* row = W_hh + (gate * Hh + jj) * Hh + 4 * kq;
            W4f[idx] = make_float4(row[0], row[1], row[2], row[3]);
        }
    }
    for (int idx = tid; idx < BPB * Hh; idx += NTHREADS)
        hb[idx] = 0.f;

    const float wir = W_ih[j];
    const float wiz = W_ih[Hh + j];
    const float win = W_ih[2 * Hh + j];
    const float cr  = b_ih[j]          + b_hh[j];
    const float cz  = b_ih[Hh + j]     + b_hh[Hh + j];
    const float cnx = b_ih[2 * Hh + j];
    const float cnh = b_hh[2 * Hh + j];

    __syncthreads();                      // publish weights + h0 to all groups

    const ulonglong2* Wr = W4 + 0 * 16 * Hh;
    const ulonglong2* Wz = W4 + 1 * 16 * Hh;
    const ulonglong2* Wn = W4 + 2 * 16 * Hh;

    float hprev[NBT];
    #pragma unroll
    for (int i = 0; i < NBT; ++i) hprev[i] = 0.f;

    int cur = 0;
    const int bar = g + 1;               // named barrier id for this 2-warp group

    for (int t = 0; t < Tt; ++t) {
        if ((t & (TX - 1)) == 0) {
            // Group stages x for its own 4 batches (128 floats / 64 threads).
            #pragma unroll
            for (int r = 0; r < 2; ++r) {
                int idx = lt + r * 64;
                int bi = idx >> 5;       // 0..3
                int tt = idx & 31;
                int bl = g * NBT + bi;
                xs[bl * TX + tt] = x[(bBase + bl) * Tt + t + tt];
            }
            grpbar(bar);
        }

        ull acc_r[NBT], acc_z[NBT], acc_n[NBT];
        #pragma unroll
        for (int i = 0; i < NBT; ++i) { acc_r[i] = 0ull; acc_z[i] = 0ull; acc_n[i] = 0ull; }

        const float* hcur = hb + cur * BPB * Hh + (g * NBT) * Hh;

        #pragma unroll
        for (int kq = 0; kq < 16; ++kq) {
            ulonglong2 wr = Wr[kq * Hh + j];
            ulonglong2 wz = Wz[kq * Hh + j];
            ulonglong2 wn = Wn[kq * Hh + j];
            #pragma unroll
            for (int i = 0; i < NBT; ++i) {
                ulonglong2 h2 = *reinterpret_cast<const ulonglong2*>(hcur + i * Hh + 4 * kq);
                acc_r[i] = ffma2(h2.x, wr.x, acc_r[i]);
                acc_r[i] = ffma2(h2.y, wr.y, acc_r[i]);
                acc_z[i] = ffma2(h2.x, wz.x, acc_z[i]);
                acc_z[i] = ffma2(h2.y, wz.y, acc_z[i]);
                acc_n[i] = ffma2(h2.x, wn.x, acc_n[i]);
                acc_n[i] = ffma2(h2.y, wn.y, acc_n[i]);
            }
        }

        const int tt = t & (TX - 1);
        float* hnext = hb + (cur ^ 1) * BPB * Hh;
        #pragma unroll
        for (int i = 0; i < NBT; ++i) {
            const int bl = g * NBT + i;
            float2 pr = unpk(acc_r[i]);
            float2 pz = unpk(acc_z[i]);
            float2 pn = unpk(acc_n[i]);
            float ar = pr.x + pr.y;
            float az = pz.x + pz.y;
            float an = pn.x + pn.y;
            float xv = xs[bl * TX + tt];
            float r  = sigmoid_f(fmaf(xv, wir, ar + cr));
            float z  = sigmoid_f(fmaf(xv, wiz, az + cz));
            float n  = tanh_f(fmaf(xv, win, cnx) + r * (an + cnh));
            float hn = fmaf(z, hprev[i] - n, n);
            hprev[i] = hn;
            hnext[bl * Hh + j] = hn;
        }
        grpbar(bar);                      // publish h(t+1) within group
        cur ^= 1;
    }

    __syncthreads();                      // all groups done before cross-group read

    if (tid < BPB) {
        const float* hl = hb + cur * BPB * Hh + tid * Hh;
        float s = b_out[0];
        #pragma unroll
        for (int k = 0; k < Hh; ++k)
            s = fmaf(hl[k], W_out[k], s);
        out[bBase + tid] = s;
    }
}

extern "C" void kernel_launch(void* const* d_in, const int* in_sizes, int n_in,
                              void* d_out, int out_size)
{
    const float* x     = (const float*)d_in[0];
    const float* W_ih  = (const float*)d_in[1];
    const float* W_hh  = (const float*)d_in[2];
    const float* b_ih  = (const float*)d_in[3];
    const float* b_hh  = (const float*)d_in[4];
    const float* W_out = (const float*)d_in[5];
    const float* b_out = (const float*)d_in[6];
    float* out = (float*)d_out;

    const size_t smem = (size_t)(3 * 16 * Hh * 4 + 2 * BPB * Hh + BPB * TX) * sizeof(float);
    cudaFuncSetAttribute(gru_persistent_kernel,
                         cudaFuncAttributeMaxDynamicSharedMemorySize, (int)smem);

    const int B = 4096;
    gru_persistent_kernel<<<B / BPB, NTHREADS, smem>>>(
        x, W_ih, W_hh, b_ih, b_hh, W_out, b_out, out);
}

// round 4
// speedup vs baseline: 2.0179x; 1.0163x over previous
#include <cuda_runtime.h>

#define Hh 64
#define Tt 512
#define Bt 4096
#define BPB 28      // batches per block (grid = 147, last block has 8)
#define NBT 7       // batches per thread (= per 64-thread group)
#define NGRP 4
#define NTHREADS 256
#define TX 32       // x timesteps staged per chunk

typedef unsigned long long ull;

__device__ __forceinline__ ull ffma2(ull a, ull b, ull c) {
    ull d;
    asm("fma.rn.f32x2 %0, %1, %2, %3;" : "=l"(d) : "l"(a), "l"(b), "l"(c));
    return d;
}
__device__ __forceinline__ float2 unpk(ull v) {
    float2 f;
    asm("mov.b64 {%0, %1}, %2;" : "=f"(f.x), "=f"(f.y) : "l"(v));
    return f;
}
__device__ __forceinline__ void grpbar(int id) {
    asm volatile("bar.sync %0, 64;" :: "r"(id) : "memory");
}

__device__ __forceinline__ float sigmoid_f(float x) {
    x = fminf(fmaxf(x, -30.f), 30.f);
    float e = __expf(-x);
    return __fdividef(1.f, 1.f + e);
}
__device__ __forceinline__ float tanh_f(float x) {
    x = fminf(fmaxf(x, -15.f), 15.f);
    float e = __expf(-2.f * x);
    return __fdividef(1.f - e, 1.f + e);
}

extern "C" __global__ void __launch_bounds__(NTHREADS, 1)
gru_persistent_kernel(const float* __restrict__ x,
                      const float* __restrict__ W_ih,
                      const float* __restrict__ W_hh,
                      const float* __restrict__ b_ih,
                      const float* __restrict__ b_hh,
                      const float* __restrict__ W_out,
                      const float* __restrict__ b_out,
                      float* __restrict__ out)
{
    extern __shared__ float sm[];
    // Weights packed as [gate][kq][j] float4 = {W[4kq..4kq+3][j]}
    ulonglong2* W4 = reinterpret_cast<ulonglong2*>(sm);     // 3*16*64 entries, 48KB
    float* hb = sm + 3 * 16 * Hh * 4;                       // [2][BPB][64]
    float* xs = hb + 2 * BPB * Hh;                          // [BPB][TX]

    const int tid = threadIdx.x;
    const int j = tid & 63;
    const int g = tid >> 6;              // 0..3 group (2 warps each)
    const int lt = tid & 63;
    const int bBase = blockIdx.x * BPB;

    // Prepack W_hh: W4f[gate*1024 + kq*64 + j] = {W_hh[(gate*64+j)*64 + 4kq + 0..3]}
    {
        float4* W4f = reinterpret_cast<float4*>(sm);
        for (int idx = tid; idx < 3 * 16 * Hh; idx += NTHREADS) {
            int gate = idx >> 10;
            int rem  = idx & 1023;
            int kq   = rem >> 6;
            int jj   = rem & 63;
            const float* row = W_hh + (gate * Hh + jj) * Hh + 4 * kq;
            W4f[idx] = make_float4(row[0], row[1], row[2], row[3]);
        }
    }
    for (int idx = tid; idx < BPB * Hh; idx += NTHREADS)
        hb[idx] = 0.f;

    const float wir = W_ih[j];
    const float wiz = W_ih[Hh + j];
    const float win = W_ih[2 * Hh + j];
    const float cr  = b_ih[j]          + b_hh[j];
    const float cz  = b_ih[Hh + j]     + b_hh[Hh + j];
    const float cnx = b_ih[2 * Hh + j];
    const float cnh = b_hh[2 * Hh + j];

    __syncthreads();                      // publish weights + h0

    const ulonglong2* Wr = W4 + 0 * 16 * Hh;
    const ulonglong2* Wz = W4 + 1 * 16 * Hh;
    const ulonglong2* Wn = W4 + 2 * 16 * Hh;

    float hprev[NBT];
    #pragma unroll
    for (int i = 0; i < NBT; ++i) hprev[i] = 0.f;

    int cur = 0;
    const int bar = g + 1;

    for (int t = 0; t < Tt; ++t) {
        if ((t & (TX - 1)) == 0) {
            // Group stages x for its own NBT batches (NBT*TX floats / 64 threads)
            #pragma unroll
            for (int r = 0; r < (NBT * TX + 63) / 64; ++r) {
                int idx = lt + r * 64;
                if (idx < NBT * TX) {
                    int bi = idx >> 5;           // 0..NBT-1
                    int tt = idx & 31;
                    int bl = g * NBT + bi;
                    int bg = bBase + bl;
                    xs[bl * TX + tt] = (bg < Bt) ? x[bg * Tt + t + tt] : 0.f;
                }
            }
            grpbar(bar);
        }

        ull acc_r[NBT], acc_z[NBT], acc_n[NBT];
        #pragma unroll
        for (int i = 0; i < NBT; ++i) { acc_r[i] = 0ull; acc_z[i] = 0ull; acc_n[i] = 0ull; }

        const float* hcur = hb + cur * BPB * Hh + (g * NBT) * Hh;

        #pragma unroll
        for (int kq = 0; kq < 16; ++kq) {
            ulonglong2 wr = Wr[kq * Hh + j];
            ulonglong2 wz = Wz[kq * Hh + j];
            ulonglong2 wn = Wn[kq * Hh + j];
            #pragma unroll
            for (int i = 0; i < NBT; ++i) {
                ulonglong2 h2 = *reinterpret_cast<const ulonglong2*>(hcur + i * Hh + 4 * kq);
                acc_r[i] = ffma2(h2.x, wr.x, acc_r[i]);
                acc_r[i] = ffma2(h2.y, wr.y, acc_r[i]);
                acc_z[i] = ffma2(h2.x, wz.x, acc_z[i]);
                acc_z[i] = ffma2(h2.y, wz.y, acc_z[i]);
                acc_n[i] = ffma2(h2.x, wn.x, acc_n[i]);
                acc_n[i] = ffma2(h2.y, wn.y, acc_n[i]);
            }
        }

        const int tt = t & (TX - 1);
        float* hnext = hb + (cur ^ 1) * BPB * Hh;
        #pragma unroll
        for (int i = 0; i < NBT; ++i) {
            const int bl = g * NBT + i;
            float2 pr = unpk(acc_r[i]);
            float2 pz = unpk(acc_z[i]);
            float2 pn = unpk(acc_n[i]);
            float ar = pr.x + pr.y;
            float az = pz.x + pz.y;
            float an = pn.x + pn.y;
            float xv = xs[bl * TX + tt];
            float r  = sigmoid_f(fmaf(xv, wir, ar + cr));
            float z  = sigmoid_f(fmaf(xv, wiz, az + cz));
            float n  = tanh_f(fmaf(xv, win, cnx) + r * (an + cnh));
            float hn = fmaf(z, hprev[i] - n, n);
            hprev[i] = hn;
            hnext[bl * Hh + j] = hn;
        }
        grpbar(bar);
        cur ^= 1;
    }

    __syncthreads();

    if (tid < BPB && bBase + tid < Bt) {
        const float* hl = hb + cur * BPB * Hh + tid * Hh;
        float s = b_out[0];
        #pragma unroll
        for (int k = 0; k < Hh; ++k)
            s = fmaf(hl[k], W_out[k], s);
        out[bBase + tid] = s;
    }
}

extern "C" void kernel_launch(void* const* d_in, const int* in_sizes, int n_in,
                              void* d_out, int out_size)
{
    const float* x     = (const float*)d_in[0];
    const float* W_ih  = (const float*)d_in[1];
    const float* W_hh  = (const float*)d_in[2];
    const float* b_ih  = (const float*)d_in[3];
    const float* b_hh  = (const float*)d_in[4];
    const float* W_out = (const float*)d_in[5];
    const float* b_out = (const float*)d_in[6];
    float* out = (float*)d_out;

    const size_t smem = (size_t)(3 * 16 * Hh * 4 + 2 * BPB * Hh + BPB * TX) * sizeof(float);
    cudaFuncSetAttribute(gru_persistent_kernel,
                         cudaFuncAttributeMaxDynamicSharedMemorySize, (int)smem);

    const int grid = (Bt + BPB - 1) / BPB;   // 147
    gru_persistent_kernel<<<grid, NTHREADS, smem>>>(
        x, W_ih, W_hh, b_ih, b_hh, W_out, b_out, out);
}